// round 1
// baseline (speedup 1.0000x reference)
#include <cuda_runtime.h>

// TrainableActivation (per-channel RBF activation) on GB300.
//
// out[n,c,h,w] = sum_{j=0..30} w[c,j] * exp(-112.5 * (x - mu_j)^2),
//   mu_j = linspace(-1, 1, 31), sigma = 2/30, inv_2s2 = 112.5.
//
// Strategy: the per-channel activation f_c(x) is a very smooth 1-D function
// (Gaussians with sigma == spacing) that vanishes for |x| > ~1.35. Build a
// per-channel linear-interpolation LUT (4096 entries over [-1.5, 1.5]),
// then apply it in a memory-bound streaming pass. Interp error ~1e-5 abs
// vs ref RMS ~1.35 -> well under the 1e-3 gate.

#define NUM_CH   64
#define NUM_W    31
#define LUT_N    4096
#define HW       16384   // 128*128
#define NBATCH   16

#define XLO  (-1.5f)
#define XHI  ( 1.5f)

// 64 * 4096 * 8B = 2 MB static device scratch (allowed: __device__ global).
__device__ float2 g_lut[NUM_CH][LUT_N];

// ---------------------------------------------------------------------------
// Kernel 1: build the per-channel LUT. One block per channel.
// Entry i stores (f(x_i), f(x_{i+1}) - f(x_i)) for fused fma interpolation.
// ---------------------------------------------------------------------------
__global__ __launch_bounds__(256) void build_lut_kernel(const float* __restrict__ w)
{
    __shared__ float sf[LUT_N];
    const int c = blockIdx.x;

    float wreg[NUM_W];
#pragma unroll
    for (int j = 0; j < NUM_W; j++) wreg[j] = w[c * NUM_W + j];

    const float h = (XHI - XLO) / (float)(LUT_N - 1);

    for (int i = threadIdx.x; i < LUT_N; i += blockDim.x) {
        const float x = XLO + (float)i * h;
        float s = 0.0f;
#pragma unroll
        for (int j = 0; j < NUM_W; j++) {
            const float mu = -1.0f + (float)j * (2.0f / 30.0f);
            const float u = x - mu;
            s += wreg[j] * __expf(-112.5f * u * u);
        }
        sf[i] = s;
    }
    __syncthreads();

    for (int i = threadIdx.x; i < LUT_N; i += blockDim.x) {
        const float d = (i < LUT_N - 1) ? (sf[i + 1] - sf[i]) : 0.0f;
        g_lut[c][i] = make_float2(sf[i], d);
    }
}

// ---------------------------------------------------------------------------
// Kernel 2: apply the LUT. Block (c, n) processes x[n][c][:][:] (16384 floats
// = 4096 float4). The channel's 32 KB LUT is staged into shared memory once.
// ---------------------------------------------------------------------------
__global__ __launch_bounds__(256) void apply_lut_kernel(const float4* __restrict__ x,
                                                        float4* __restrict__ y)
{
    __shared__ float2 lut[LUT_N];

    const int c = blockIdx.x;
    const int n = blockIdx.y;

    // Stage LUT: 4096 float2 = 2048 float4.
    {
        const float4* src = reinterpret_cast<const float4*>(g_lut[c]);
        float4* dst = reinterpret_cast<float4*>(lut);
        for (int i = threadIdx.x; i < LUT_N / 2; i += 256) dst[i] = src[i];
    }
    __syncthreads();

    const float INV_H = (float)(LUT_N - 1) / (XHI - XLO);
    const float TMAX  = (float)(LUT_N - 1);

    const int base = (n * NUM_CH + c) * (HW / 4);

#pragma unroll 4
    for (int i = threadIdx.x; i < HW / 4; i += 256) {
        const float4 v = x[base + i];
        float4 o;

        {
            float t = (v.x - XLO) * INV_H;
            t = fminf(fmaxf(t, 0.0f), TMAX);
            const int   idx = (int)t;
            const float fr  = t - (float)idx;
            const float2 e  = lut[idx];
            o.x = fmaf(fr, e.y, e.x);
        }
        {
            float t = (v.y - XLO) * INV_H;
            t = fminf(fmaxf(t, 0.0f), TMAX);
            const int   idx = (int)t;
            const float fr  = t - (float)idx;
            const float2 e  = lut[idx];
            o.y = fmaf(fr, e.y, e.x);
        }
        {
            float t = (v.z - XLO) * INV_H;
            t = fminf(fmaxf(t, 0.0f), TMAX);
            const int   idx = (int)t;
            const float fr  = t - (float)idx;
            const float2 e  = lut[idx];
            o.z = fmaf(fr, e.y, e.x);
        }
        {
            float t = (v.w - XLO) * INV_H;
            t = fminf(fmaxf(t, 0.0f), TMAX);
            const int   idx = (int)t;
            const float fr  = t - (float)idx;
            const float2 e  = lut[idx];
            o.w = fmaf(fr, e.y, e.x);
        }

        y[base + i] = o;
    }
}

// ---------------------------------------------------------------------------
// Launch: two dependent kernels on the default stream (graph-capturable,
// allocation-free, deterministic).
// ---------------------------------------------------------------------------
extern "C" void kernel_launch(void* const* d_in, const int* in_sizes, int n_in,
                              void* d_out, int out_size)
{
    const float* x = (const float*)d_in[0];   // [16, 64, 128, 128] fp32
    const float* w = (const float*)d_in[1];   // [64, 31] fp32

    build_lut_kernel<<<NUM_CH, 256>>>(w);

    dim3 grid(NUM_CH, NBATCH);
    apply_lut_kernel<<<grid, 256>>>(reinterpret_cast<const float4*>(x),
                                    reinterpret_cast<float4*>(d_out));
}

// round 2
// speedup vs baseline: 1.4912x; 1.4912x over previous
#include <cuda_runtime.h>

// TrainableActivation (per-channel RBF activation) on GB300 — round 2.
//
// out[n,c,h,w] = sum_{j=0..30} w[c,j] * exp(-112.5 * (x - mu_j)^2)
//
// Per-channel linear-interp LUT. Round-2 changes vs round 1:
//  * LUT 4096 -> 2048 entries (16 KB smem): occupancy 6 -> 8 blocks/SM
//    (warp-limited, 100%), and 1024 blocks now fit in ONE wave (no tail).
//  * Streaming cache hints (__ldcs/__stcs): x/y have zero reuse.
//  * Deeper unroll for more in-flight LDGs.
// Predicted interp error ~7e-6 relative (gate 1e-3).

#define NUM_CH   64
#define NUM_W    31
#define LUT_N    2048
#define HW       16384   // 128*128
#define NBATCH   16

#define XLO  (-1.5f)
#define XHI  ( 1.5f)

// 64 * 2048 * 8B = 1 MB static device scratch.
__device__ float2 g_lut[NUM_CH][LUT_N];

// ---------------------------------------------------------------------------
// Kernel 1: build the per-channel LUT. One block per channel.
// Entry i stores (f(x_i), f(x_{i+1}) - f(x_i)) for fused fma interpolation.
// ---------------------------------------------------------------------------
__global__ __launch_bounds__(256) void build_lut_kernel(const float* __restrict__ w)
{
    __shared__ float sf[LUT_N];
    const int c = blockIdx.x;

    float wreg[NUM_W];
#pragma unroll
    for (int j = 0; j < NUM_W; j++) wreg[j] = w[c * NUM_W + j];

    const float h = (XHI - XLO) / (float)(LUT_N - 1);

    for (int i = threadIdx.x; i < LUT_N; i += blockDim.x) {
        const float x = XLO + (float)i * h;
        float s = 0.0f;
#pragma unroll
        for (int j = 0; j < NUM_W; j++) {
            const float mu = -1.0f + (float)j * (2.0f / 30.0f);
            const float u = x - mu;
            s += wreg[j] * __expf(-112.5f * u * u);
        }
        sf[i] = s;
    }
    __syncthreads();

    for (int i = threadIdx.x; i < LUT_N; i += blockDim.x) {
        const float d = (i < LUT_N - 1) ? (sf[i + 1] - sf[i]) : 0.0f;
        g_lut[c][i] = make_float2(sf[i], d);
    }
}

// ---------------------------------------------------------------------------
// Kernel 2: apply the LUT. Block (c, n) processes x[n][c][:][:] (16384 floats
// = 4096 float4). The channel's 16 KB LUT is staged into shared memory once.
// ---------------------------------------------------------------------------
__global__ __launch_bounds__(256) void apply_lut_kernel(const float4* __restrict__ x,
                                                        float4* __restrict__ y)
{
    __shared__ float2 lut[LUT_N];

    const int c = blockIdx.x;
    const int n = blockIdx.y;

    // Stage LUT: 2048 float2 = 1024 float4 -> one float4 per thread x4.
    {
        const float4* src = reinterpret_cast<const float4*>(g_lut[c]);
        float4* dst = reinterpret_cast<float4*>(lut);
#pragma unroll
        for (int k = 0; k < LUT_N / 2 / 256; k++)
            dst[k * 256 + threadIdx.x] = src[k * 256 + threadIdx.x];
    }
    __syncthreads();

    const float INV_H = (float)(LUT_N - 1) / (XHI - XLO);
    const float TMAX  = (float)(LUT_N - 1);

    const int base = (n * NUM_CH + c) * (HW / 4);

#pragma unroll 8
    for (int i = threadIdx.x; i < HW / 4; i += 256) {
        const float4 v = __ldcs(&x[base + i]);
        float4 o;

        {
            float t = fminf(fmaxf((v.x - XLO) * INV_H, 0.0f), TMAX);
            const int   idx = (int)t;
            const float fr  = t - (float)idx;
            const float2 e  = lut[idx];
            o.x = fmaf(fr, e.y, e.x);
        }
        {
            float t = fminf(fmaxf((v.y - XLO) * INV_H, 0.0f), TMAX);
            const int   idx = (int)t;
            const float fr  = t - (float)idx;
            const float2 e  = lut[idx];
            o.y = fmaf(fr, e.y, e.x);
        }
        {
            float t = fminf(fmaxf((v.z - XLO) * INV_H, 0.0f), TMAX);
            const int   idx = (int)t;
            const float fr  = t - (float)idx;
            const float2 e  = lut[idx];
            o.z = fmaf(fr, e.y, e.x);
        }
        {
            float t = fminf(fmaxf((v.w - XLO) * INV_H, 0.0f), TMAX);
            const int   idx = (int)t;
            const float fr  = t - (float)idx;
            const float2 e  = lut[idx];
            o.w = fmaf(fr, e.y, e.x);
        }

        __stcs(&y[base + i], o);
    }
}

// ---------------------------------------------------------------------------
// Launch: two dependent kernels on the default stream (graph-capturable,
// allocation-free, deterministic).
// ---------------------------------------------------------------------------
extern "C" void kernel_launch(void* const* d_in, const int* in_sizes, int n_in,
                              void* d_out, int out_size)
{
    const float* x = (const float*)d_in[0];   // [16, 64, 128, 128] fp32
    const float* w = (const float*)d_in[1];   // [64, 31] fp32

    build_lut_kernel<<<NUM_CH, 256>>>(w);

    dim3 grid(NUM_CH, NBATCH);
    apply_lut_kernel<<<grid, 256>>>(reinterpret_cast<const float4*>(x),
                                    reinterpret_cast<float4*>(d_out));
}

// round 3
// speedup vs baseline: 1.7193x; 1.1530x over previous
#include <cuda_runtime.h>
#include <cuda_fp16.h>

// TrainableActivation (per-channel RBF activation) on GB300 — round 3.
//
// out[n,c,h,w] = sum_{j=0..30} w[c,j] * exp(-112.5 * (x - mu_j)^2)
//
// Round-3 changes vs round 2 (23us apply, DRAM 46.7%, L1 63.7%):
//  * cp.async (LDGSTS) 4-stage pipelined input staging -> DRAM latency
//    decoupled from registers; ~90KB in flight per SM (was ~2KB).
//  * LUT entries packed as half2(value, delta): gather is LDS.32 (1 bank
//    touch/lane, ~2x fewer replays than LDS.64), smem LUT 8KB.
//    Adds ~2.8e-4 RMS rel error (gate 1e-3, 3.5x margin).
//  * build kernel parallelized 64 -> 512 blocks; apply grid 1024 -> 2048
//    (half-planes) to smooth the wave tail.

#define NUM_CH   64
#define NUM_W    31
#define LUT_N    2048
#define HW       16384    // 128*128
#define NBATCH   16

#define XLO  (-1.5f)
#define XHI  ( 1.5f)

#define NSTAGE        4
#define TILE_F4       256      // float4 per tile == blockDim
#define TILES_PER_BLK 8        // half plane: 2048 float4 / 256

// 64 * 2048 * 4B = 512 KB static device scratch (L2-resident).
__device__ __half2 g_lut[NUM_CH][LUT_N];

// ---------------------------------------------------------------------------
// Kernel 1: build the per-channel LUT. Grid (64, 8): block (c, seg) computes
// 256 entries. Entry i packs (f(x_i), f(x_{i+1}) - f(x_i)) as half2.
// ---------------------------------------------------------------------------
__global__ __launch_bounds__(256) void build_lut_kernel(const float* __restrict__ w)
{
    __shared__ float sf[257];
    const int c    = blockIdx.x;
    const int base = blockIdx.y * 256;
    const int tid  = threadIdx.x;

    float wreg[NUM_W];
#pragma unroll
    for (int j = 0; j < NUM_W; j++) wreg[j] = w[c * NUM_W + j];

    const float h = (XHI - XLO) / (float)(LUT_N - 1);

    // f at entries base..base+256 (one extra for the forward delta).
    for (int k = tid; k < 257; k += 256) {
        const int i = base + k;
        float s = 0.0f;
        if (i < LUT_N) {
            const float x = XLO + (float)i * h;
#pragma unroll
            for (int j = 0; j < NUM_W; j++) {
                const float mu = -1.0f + (float)j * (2.0f / 30.0f);
                const float u = x - mu;
                s += wreg[j] * __expf(-112.5f * u * u);
            }
        }
        sf[k] = s;
    }
    __syncthreads();

    const int i = base + tid;
    const float d = (i < LUT_N - 1) ? (sf[tid + 1] - sf[tid]) : 0.0f;
    g_lut[c][i] = __floats2half2_rn(sf[tid], d);   // .x = value, .y = delta
}

// ---------------------------------------------------------------------------
// Kernel 2: apply. Grid (64, 16, 2): block (c, n, z) processes half of
// x[n][c][:][:] (2048 float4) via a 4-stage cp.async pipeline.
// ---------------------------------------------------------------------------
struct __align__(16) Smem {
    __half2 lut[LUT_N];               // 8 KB
    float4  tiles[NSTAGE][TILE_F4];   // 16 KB
};

__global__ __launch_bounds__(256) void apply_lut_kernel(const float4* __restrict__ x,
                                                        float4* __restrict__ y)
{
    __shared__ Smem s;

    const int c   = blockIdx.x;
    const int n   = blockIdx.y;
    const int z   = blockIdx.z;
    const int tid = threadIdx.x;

    const int base = (n * NUM_CH + c) * (HW / 4) + z * (TILES_PER_BLK * TILE_F4);
    const float4* src = x + base;
    float4*       dst = y + base;

    // Prologue: kick off tiles 0..NSTAGE-2 immediately (get DRAM going).
#pragma unroll
    for (int t = 0; t < NSTAGE - 1; t++) {
        unsigned daddr = (unsigned)__cvta_generic_to_shared(&s.tiles[t][tid]);
        asm volatile("cp.async.cg.shared.global [%0], [%1], 16;"
                     :: "r"(daddr), "l"(src + t * TILE_F4 + tid));
        asm volatile("cp.async.commit_group;");
    }

    // Stage the 8 KB LUT (512 float4; 2 per thread). L2-resident source.
    {
        const float4* lsrc = reinterpret_cast<const float4*>(g_lut[c]);
        float4* ldst = reinterpret_cast<float4*>(s.lut);
        ldst[tid]       = lsrc[tid];
        ldst[tid + 256] = lsrc[tid + 256];
    }

    const float INV_H = (float)(LUT_N - 1) / (XHI - XLO);
    const float TMAX  = (float)(LUT_N - 1);

    for (int t = 0; t < TILES_PER_BLK; t++) {
        // Tiles <= t have landed once at most NSTAGE-2 groups remain pending.
        asm volatile("cp.async.wait_group %0;" :: "n"(NSTAGE - 2));
        __syncthreads();   // tile t visible to all; everyone done reading t-1

        // Issue tile t+3 into the buffer tile t-1 just vacated.
        if (t + NSTAGE - 1 < TILES_PER_BLK) {
            unsigned daddr = (unsigned)__cvta_generic_to_shared(
                &s.tiles[(t + NSTAGE - 1) % NSTAGE][tid]);
            asm volatile("cp.async.cg.shared.global [%0], [%1], 16;"
                         :: "r"(daddr), "l"(src + (t + NSTAGE - 1) * TILE_F4 + tid));
        }
        asm volatile("cp.async.commit_group;");   // always: keeps group count uniform

        const float4 v = s.tiles[t % NSTAGE][tid];
        float4 o;
        {
            float tt = fminf(fmaxf((v.x - XLO) * INV_H, 0.0f), TMAX);
            const int idx = (int)tt;
            const float2 e = __half22float2(s.lut[idx]);
            o.x = fmaf(tt - (float)idx, e.y, e.x);
        }
        {
            float tt = fminf(fmaxf((v.y - XLO) * INV_H, 0.0f), TMAX);
            const int idx = (int)tt;
            const float2 e = __half22float2(s.lut[idx]);
            o.y = fmaf(tt - (float)idx, e.y, e.x);
        }
        {
            float tt = fminf(fmaxf((v.z - XLO) * INV_H, 0.0f), TMAX);
            const int idx = (int)tt;
            const float2 e = __half22float2(s.lut[idx]);
            o.z = fmaf(tt - (float)idx, e.y, e.x);
        }
        {
            float tt = fminf(fmaxf((v.w - XLO) * INV_H, 0.0f), TMAX);
            const int idx = (int)tt;
            const float2 e = __half22float2(s.lut[idx]);
            o.w = fmaf(tt - (float)idx, e.y, e.x);
        }

        __stcs(dst + t * TILE_F4 + tid, o);
    }
}

// ---------------------------------------------------------------------------
// Launch: two dependent kernels (graph-capturable, allocation-free).
// ---------------------------------------------------------------------------
extern "C" void kernel_launch(void* const* d_in, const int* in_sizes, int n_in,
                              void* d_out, int out_size)
{
    const float* x = (const float*)d_in[0];   // [16, 64, 128, 128] fp32
    const float* w = (const float*)d_in[1];   // [64, 31] fp32

    build_lut_kernel<<<dim3(NUM_CH, LUT_N / 256), 256>>>(w);

    apply_lut_kernel<<<dim3(NUM_CH, NBATCH, 2), 256>>>(
        reinterpret_cast<const float4*>(x),
        reinterpret_cast<float4*>(d_out));
}

// round 4
// speedup vs baseline: 1.7639x; 1.0259x over previous
#include <cuda_runtime.h>
#include <cuda_fp16.h>

// TrainableActivation (per-channel RBF activation) on GB300 — round 4.
//
// out[n,c,h,w] = sum_{j=0..30} w[c,j] * exp(-112.5 * (x - mu_j)^2)
//
// Round-4 changes vs round 3 (apply 19.6us, DRAM 51.9%, L1 63.6%):
//  * Barrier-free cp.async pipeline: each thread stages and consumes its OWN
//    16B/tile -> per-thread wait_group is sufficient, no per-tile
//    __syncthreads (removes the 8x warp convoy).
//  * LUT: 1024 entries (interp err ~3e-5, under fp16's 2.1e-4), 4-way
//    bank-replicated in smem (entry i at words 4i..4i+3, lane reads copy
//    lane&3) -> gather replay ~3.9 -> ~2.9 wavefronts.
//  * Replication built in smem from a 4KB cp.async-staged compact LUT
//    (L2 LUT traffic stays ~8MB). smem 36KB -> 6 blocks/SM.

#define NUM_CH   64
#define NUM_W    31
#define LUT_N    1024
#define REP      4
#define HW       16384    // 128*128
#define NBATCH   16

#define XLO  (-1.5f)
#define XHI  ( 1.5f)

#define NSTAGE        4
#define TILE_F4       256      // float4 per tile == blockDim
#define TILES_PER_BLK 8        // half plane: 2048 float4 / 256

// 64 * 1024 * 4B = 256 KB compact LUT (L2-resident after build).
__device__ __align__(16) __half2 g_lut[NUM_CH][LUT_N];

// ---------------------------------------------------------------------------
// Kernel 1: build the compact per-channel LUT. Grid (64, 4): block (c, seg)
// computes 256 entries. Entry i packs (f(x_i), f(x_{i+1})-f(x_i)) as half2.
// ---------------------------------------------------------------------------
__global__ __launch_bounds__(256) void build_lut_kernel(const float* __restrict__ w)
{
    __shared__ float sf[257];
    const int c    = blockIdx.x;
    const int base = blockIdx.y * 256;
    const int tid  = threadIdx.x;

    float wreg[NUM_W];
#pragma unroll
    for (int j = 0; j < NUM_W; j++) wreg[j] = w[c * NUM_W + j];

    const float h = (XHI - XLO) / (float)(LUT_N - 1);

    for (int k = tid; k < 257; k += 256) {
        const int i = base + k;
        float s = 0.0f;
        if (i < LUT_N) {
            const float x = XLO + (float)i * h;
#pragma unroll
            for (int j = 0; j < NUM_W; j++) {
                const float mu = -1.0f + (float)j * (2.0f / 30.0f);
                const float u = x - mu;
                s += wreg[j] * __expf(-112.5f * u * u);
            }
        }
        sf[k] = s;
    }
    __syncthreads();

    const int i = base + tid;
    const float d = (i < LUT_N - 1) ? (sf[tid + 1] - sf[tid]) : 0.0f;
    g_lut[c][i] = __floats2half2_rn(sf[tid], d);   // .x = value, .y = delta
}

// ---------------------------------------------------------------------------
// Kernel 2: apply. Grid (64, 16, 2): block (c, n, z) processes half of
// x[n][c][:][:] (2048 float4) via a barrier-free 4-stage cp.async pipeline.
// ---------------------------------------------------------------------------
struct __align__(16) Smem {
    __half2 lut[LUT_N * REP];         // 16 KB, 4-way bank-replicated
    float4  tiles[NSTAGE][TILE_F4];   // 16 KB
    __half2 compact[LUT_N];           //  4 KB staging for the LUT
};

__device__ __forceinline__ void cp16(void* dst_smem, const void* src_gmem)
{
    unsigned d = (unsigned)__cvta_generic_to_shared(dst_smem);
    asm volatile("cp.async.cg.shared.global [%0], [%1], 16;" :: "r"(d), "l"(src_gmem));
}
__device__ __forceinline__ void cp_commit()
{
    asm volatile("cp.async.commit_group;");
}

__global__ __launch_bounds__(256) void apply_lut_kernel(const float4* __restrict__ x,
                                                        float4* __restrict__ y)
{
    __shared__ Smem s;

    const int c   = blockIdx.x;
    const int n   = blockIdx.y;
    const int z   = blockIdx.z;
    const int tid = threadIdx.x;

    const int base = (n * NUM_CH + c) * (HW / 4) + z * (TILES_PER_BLK * TILE_F4);
    const float4* src = x + base;
    float4*       dst = y + base;

    // Group 0: compact LUT (4 KB, 16B/thread). Groups 1..3: tiles 0..2.
    cp16(&s.compact[tid * 4], &g_lut[c][tid * 4]);
    cp_commit();
#pragma unroll
    for (int t = 0; t < NSTAGE - 1; t++) {
        cp16(&s.tiles[t][tid], src + t * TILE_F4 + tid);
        cp_commit();
    }

    // Wait for the LUT group (3 newest = tiles may stay in flight), publish
    // it block-wide, and expand 4-way: entry i -> words 4i..4i+3.
    asm volatile("cp.async.wait_group 3;" ::: "memory");
    __syncthreads();
    {
        const unsigned* cw = reinterpret_cast<const unsigned*>(s.compact);
        uint4* lr = reinterpret_cast<uint4*>(s.lut);
#pragma unroll
        for (int m = 0; m < LUT_N / 256; m++) {
            const unsigned u = cw[tid + 256 * m];        // conflict-free LDS.32
            lr[tid + 256 * m] = make_uint4(u, u, u, u);  // consecutive STS.128
        }
    }
    __syncthreads();   // last block-wide barrier; loop below is barrier-free

    const float INV_H = (float)(LUT_N - 1) / (XHI - XLO);
    const float OFF   = -XLO * INV_H;
    const float TMAX  = (float)(LUT_N - 1);

    // Lane reads its own replica: word index = idx*4 + (lane&3).
    const __half2* lp = s.lut + (tid & 3);

    for (int t = 0; t < TILES_PER_BLK; t++) {
        // Issue tile t+3 (into the slot this thread finished reading at t-1).
        if (t + NSTAGE - 1 < TILES_PER_BLK)
            cp16(&s.tiles[(t + NSTAGE - 1) & (NSTAGE - 1)][tid],
                 src + (t + NSTAGE - 1) * TILE_F4 + tid);
        cp_commit();   // uniform group count even when no copy issued

        // All but the 3 newest groups done => tile t (this thread's bytes).
        asm volatile("cp.async.wait_group 3;" ::: "memory");

        const float4 v = s.tiles[t & (NSTAGE - 1)][tid];
        float4 o;
        {
            const float tt = fminf(fmaxf(fmaf(v.x, INV_H, OFF), 0.0f), TMAX);
            const int idx = (int)tt;
            const float2 e = __half22float2(lp[idx * REP]);
            o.x = fmaf(tt - (float)idx, e.y, e.x);
        }
        {
            const float tt = fminf(fmaxf(fmaf(v.y, INV_H, OFF), 0.0f), TMAX);
            const int idx = (int)tt;
            const float2 e = __half22float2(lp[idx * REP]);
            o.y = fmaf(tt - (float)idx, e.y, e.x);
        }
        {
            const float tt = fminf(fmaxf(fmaf(v.z, INV_H, OFF), 0.0f), TMAX);
            const int idx = (int)tt;
            const float2 e = __half22float2(lp[idx * REP]);
            o.z = fmaf(tt - (float)idx, e.y, e.x);
        }
        {
            const float tt = fminf(fmaxf(fmaf(v.w, INV_H, OFF), 0.0f), TMAX);
            const int idx = (int)tt;
            const float2 e = __half22float2(lp[idx * REP]);
            o.w = fmaf(tt - (float)idx, e.y, e.x);
        }

        __stcs(dst + t * TILE_F4 + tid, o);
    }
}

// ---------------------------------------------------------------------------
// Launch: two dependent kernels (graph-capturable, allocation-free).
// ---------------------------------------------------------------------------
extern "C" void kernel_launch(void* const* d_in, const int* in_sizes, int n_in,
                              void* d_out, int out_size)
{
    const float* x = (const float*)d_in[0];   // [16, 64, 128, 128] fp32
    const float* w = (const float*)d_in[1];   // [64, 31] fp32

    build_lut_kernel<<<dim3(NUM_CH, LUT_N / 256), 256>>>(w);

    apply_lut_kernel<<<dim3(NUM_CH, NBATCH, 2), 256>>>(
        reinterpret_cast<const float4*>(x),
        reinterpret_cast<float4*>(d_out));
}